// round 1
// baseline (speedup 1.0000x reference)
#include <cuda_runtime.h>
#include <cstdint>

// Problem constants
//   B=8, R=32  -> N = 8192 points
//   E=8 groups, L=16 levels, F=4 feats/level, T=2^17 entries/level
//   MLP: 64 -> 64 -> 64 -> 32, leaky_relu(0.2)
// Inputs (metadata order): feat_coords[8,16,32,32], tables[8,16,131072,4],
//   w1[8,64,64], b1[8,64], w2[8,64,64], b2[8,64], w3[8,64,32], b3[8,32]
// Output: [8,32,32,256] fp32, out[b,y,x, e*32+o]

#define TMASK 0x1FFFFu
#define TSIZE (1u << 17)

// res_l = floor(16 * 2^(l/15)); l=15 is exactly 32 in exact math (flip to 31 if ref disagrees)
__constant__ float c_res[16] = {16.f,16.f,17.f,18.f,19.f,20.f,21.f,22.f,
                                23.f,24.f,25.f,26.f,27.f,29.f,30.f,32.f};

__device__ __forceinline__ float lrelu(float v) { return v > 0.f ? v : 0.2f * v; }

__global__ void __launch_bounds__(128, 3) hash_mlp_kernel(
    const float*  __restrict__ fc,      // [8,16,32,32]
    const float4* __restrict__ tables,  // [8,16,T] of float4
    const float*  __restrict__ w1,      // [8,64,64]
    const float*  __restrict__ b1,      // [8,64]
    const float*  __restrict__ w2,      // [8,64,64]
    const float*  __restrict__ b2,      // [8,64]
    const float*  __restrict__ w3,      // [8,64,32]
    const float*  __restrict__ b3,      // [8,32]
    float*        __restrict__ out)     // [8,32,32,256]
{
    __shared__ __align__(16) float s_w1[64 * 64];
    __shared__ __align__(16) float s_w2[64 * 64];
    __shared__ __align__(16) float s_w3[64 * 32];
    __shared__ float s_b1[64], s_b2[64], s_b3[32];

    const int e   = blockIdx.y;
    const int tid = threadIdx.x;

    // Stage this group's weights into shared (coalesced)
    {
        const float* w1g = w1 + e * 4096;
        const float* w2g = w2 + e * 4096;
        const float* w3g = w3 + e * 2048;
        #pragma unroll
        for (int i = 0; i < 32; i++) s_w1[i * 128 + tid] = w1g[i * 128 + tid];
        #pragma unroll
        for (int i = 0; i < 32; i++) s_w2[i * 128 + tid] = w2g[i * 128 + tid];
        #pragma unroll
        for (int i = 0; i < 16; i++) s_w3[i * 128 + tid] = w3g[i * 128 + tid];
        if (tid < 64) {
            s_b1[tid] = b1[e * 64 + tid];
            s_b2[tid] = b2[e * 64 + tid];
        } else if (tid < 96) {
            s_b3[tid - 64] = b3[e * 32 + (tid - 64)];
        }
    }
    __syncthreads();

    const int n  = blockIdx.x * 128 + tid;      // point id 0..8191
    const int b  = n >> 10;                     // batch
    const int iy = (n >> 5) & 31;
    const int ix = n & 31;

    // 4D input coords: (fc0, fc1, x, y)
    const float c0 = __ldg(&fc[((b * 16 + 2 * e) * 32 + iy) * 32 + ix]);
    const float c1 = __ldg(&fc[((b * 16 + 2 * e + 1) * 32 + iy) * 32 + ix]);
    const float c2 = ((float)ix + 0.5f) * (1.0f / 32.0f);
    const float c3 = ((float)iy + 0.5f) * (1.0f / 32.0f);

    const float4* tbl = tables + (size_t)e * 16 * TSIZE;

    // Layer-1 accumulator; level features are folded in as they are gathered
    float h1[64];
    #pragma unroll
    for (int j = 0; j < 64; j++) h1[j] = s_b1[j];

    #pragma unroll 1
    for (int l = 0; l < 16; l++) {
        const float res = c_res[l];
        const float x0 = c0 * res, x1 = c1 * res, x2 = c2 * res, x3 = c3 * res;
        const float p0 = floorf(x0), p1 = floorf(x1), p2 = floorf(x2), p3 = floorf(x3);
        const float f0 = x0 - p0, f1 = x1 - p1, f2 = x2 - p2, f3 = x3 - p3;
        const float g0 = 1.f - f0, g1 = 1.f - f1, g2 = 1.f - f2, g3 = 1.f - f3;
        const uint32_t u0 = (uint32_t)p0, u1 = (uint32_t)p1,
                       u2 = (uint32_t)p2, u3 = (uint32_t)p3;

        // per-dim hash contributions for offset 0 / 1 (uint32 wraparound ok)
        const uint32_t a0 = u0;                         const uint32_t A0 = a0 + 1u;
        const uint32_t a1 = u1 * 2654435761u;           const uint32_t A1 = a1 + 2654435761u;
        const uint32_t a2 = u2 * 805459861u;            const uint32_t A2 = a2 + 805459861u;
        const uint32_t a3 = u3 * 3674653429u;           const uint32_t A3 = a3 + 3674653429u;

        float acc0 = 0.f, acc1 = 0.f, acc2 = 0.f, acc3 = 0.f;
        #pragma unroll
        for (int cr = 0; cr < 16; cr++) {
            const uint32_t h = (((cr & 1) ? A0 : a0) ^ ((cr & 2) ? A1 : a1) ^
                                ((cr & 4) ? A2 : a2) ^ ((cr & 8) ? A3 : a3)) & TMASK;
            const float w = ((cr & 1) ? f0 : g0) * ((cr & 2) ? f1 : g1) *
                            ((cr & 4) ? f2 : g2) * ((cr & 8) ? f3 : g3);
            const float4 v = __ldg(&tbl[(size_t)l * TSIZE + h]);
            acc0 = fmaf(w, v.x, acc0);
            acc1 = fmaf(w, v.y, acc1);
            acc2 = fmaf(w, v.z, acc2);
            acc3 = fmaf(w, v.w, acc3);
        }

        // Fold this level's 4 features into layer-1 accumulators
        const float4* wl = (const float4*)(s_w1 + l * 4 * 64);
        #pragma unroll
        for (int j = 0; j < 16; j++) {
            const float4 wa = wl[j];
            const float4 wb = wl[16 + j];
            const float4 wc = wl[32 + j];
            const float4 wd = wl[48 + j];
            h1[4 * j + 0] = fmaf(acc0, wa.x, fmaf(acc1, wb.x, fmaf(acc2, wc.x, fmaf(acc3, wd.x, h1[4 * j + 0]))));
            h1[4 * j + 1] = fmaf(acc0, wa.y, fmaf(acc1, wb.y, fmaf(acc2, wc.y, fmaf(acc3, wd.y, h1[4 * j + 1]))));
            h1[4 * j + 2] = fmaf(acc0, wa.z, fmaf(acc1, wb.z, fmaf(acc2, wc.z, fmaf(acc3, wd.z, h1[4 * j + 2]))));
            h1[4 * j + 3] = fmaf(acc0, wa.w, fmaf(acc1, wb.w, fmaf(acc2, wc.w, fmaf(acc3, wd.w, h1[4 * j + 3]))));
        }
    }

    // activation of layer 1
    #pragma unroll
    for (int k = 0; k < 64; k++) h1[k] = lrelu(h1[k]);

    // layer 2
    float h2[64];
    #pragma unroll
    for (int j = 0; j < 64; j++) h2[j] = s_b2[j];
    #pragma unroll
    for (int k = 0; k < 64; k++) {
        const float a = h1[k];
        const float4* wv = (const float4*)(s_w2 + k * 64);
        #pragma unroll
        for (int j = 0; j < 16; j++) {
            const float4 w = wv[j];
            h2[4 * j + 0] = fmaf(a, w.x, h2[4 * j + 0]);
            h2[4 * j + 1] = fmaf(a, w.y, h2[4 * j + 1]);
            h2[4 * j + 2] = fmaf(a, w.z, h2[4 * j + 2]);
            h2[4 * j + 3] = fmaf(a, w.w, h2[4 * j + 3]);
        }
    }

    // layer 3
    float o[32];
    #pragma unroll
    for (int j = 0; j < 32; j++) o[j] = s_b3[j];
    #pragma unroll
    for (int k = 0; k < 64; k++) {
        const float a = lrelu(h2[k]);
        const float4* wv = (const float4*)(s_w3 + k * 32);
        #pragma unroll
        for (int j = 0; j < 8; j++) {
            const float4 w = wv[j];
            o[4 * j + 0] = fmaf(a, w.x, o[4 * j + 0]);
            o[4 * j + 1] = fmaf(a, w.y, o[4 * j + 1]);
            o[4 * j + 2] = fmaf(a, w.z, o[4 * j + 2]);
            o[4 * j + 3] = fmaf(a, w.w, o[4 * j + 3]);
        }
    }

    // out[b, iy, ix, e*32 + o] ; n*256 + e*32 is 128B aligned
    float4* op = (float4*)(out + (size_t)n * 256 + e * 32);
    #pragma unroll
    for (int j = 0; j < 8; j++) {
        op[j] = make_float4(o[4 * j + 0], o[4 * j + 1], o[4 * j + 2], o[4 * j + 3]);
    }
}

extern "C" void kernel_launch(void* const* d_in, const int* in_sizes, int n_in,
                              void* d_out, int out_size) {
    const float*  fc     = (const float*)d_in[0];
    const float4* tables = (const float4*)d_in[1];
    const float*  w1     = (const float*)d_in[2];
    const float*  b1     = (const float*)d_in[3];
    const float*  w2     = (const float*)d_in[4];
    const float*  b2     = (const float*)d_in[5];
    const float*  w3     = (const float*)d_in[6];
    const float*  b3     = (const float*)d_in[7];

    dim3 grid(64, 8);   // 64 tiles of 128 points  x  8 groups
    hash_mlp_kernel<<<grid, 128>>>(fc, tables, w1, b1, w2, b2, w3, b3, (float*)d_out);
}